// round 8
// baseline (speedup 1.0000x reference)
#include <cuda_runtime.h>
#include <math.h>

#define DEG   16
#define D     64
#define D2    128
#define BQ    1024
#define NQ    2058
#define XPAD  20           /* row stride (words) for slot-dim arrays: conflict-free */
#define GRID  444          /* 3 blocks/SM * 148 SMs, persistent */

// ---------------------------------------------------------------------------
__global__ __launch_bounds__(256)
void k_fused(const float* __restrict__ feat,
             const int*   __restrict__ adj,
             const int*   __restrict__ in1,
             const int*   __restrict__ in2,
             const int*   __restrict__ neg,
             const float* __restrict__ W1,
             const float* __restrict__ b1,
             const float* __restrict__ W2,
             const float* __restrict__ b2,
             float*       __restrict__ out) {
    __shared__ __align__(16) float xq[2 * D][XPAD];      // [i][slot] 10 KB
    __shared__ __align__(16) float pr[4][D][XPAD];       // partial dots 20 KB
    __shared__ __align__(16) float part[4][D];           // slot-quad tanh sums
    __shared__ __align__(16) float x2s[2 * D];           // hop-2 input
    __shared__ __align__(16) float yp[2][D2];            // hop-2 half partials
    __shared__ float b1s[D];
    __shared__ float red[4];

    int tid = threadIdx.x;
    int jj  = tid & 63;      // hop-1 output column
    int kk  = tid >> 6;      // i-chunk / slot-quad / gather-group (0..3)
    int col = tid & 127;     // hop-2 output column
    int hlf = tid >> 7;      // hop-2 i-half

    // ---- stage W1 chunk into registers (once per block) ------------------
    float Wreg[32];
    {
        const float4* ws = (const float4*)(W1 + jj * (2 * D) + kk * 32);
        #pragma unroll
        for (int r = 0; r < 8; ++r) {
            float4 v = ws[r];
            Wreg[r * 4 + 0] = v.x; Wreg[r * 4 + 1] = v.y;
            Wreg[r * 4 + 2] = v.z; Wreg[r * 4 + 3] = v.w;
        }
    }
    if (tid < D) b1s[tid] = b1[tid];

    for (int q = blockIdx.x; q < NQ; q += GRID) {
        int qn = (q < BQ) ? in1[q] : (q < 2 * BQ) ? in2[q - BQ] : neg[q - 2 * BQ];

        // ---------------- gather: group kk handles slots kk*4..kk*4+3 -----
        if (tid < D) x2s[tid] = feat[qn * D + tid];      // self features

        {
            int4 nn4 = *(const int4*)(adj + qn * DEG + kk * 4);  // broadcast
            int nodes[4] = {nn4.x, nn4.y, nn4.z, nn4.w};
            float self[4], nsum[4];
            #pragma unroll
            for (int s = 0; s < 4; ++s) {
                int node = nodes[s];
                self[s] = feat[node * D + jj];
                const int4* a4 = (const int4*)(adj + node * DEG);
                int4 a0 = a4[0], a1 = a4[1], a2 = a4[2], a3 = a4[3];
                float t0 = feat[a0.x * D + jj] + feat[a0.y * D + jj]
                         + feat[a0.z * D + jj] + feat[a0.w * D + jj];
                float t1 = feat[a1.x * D + jj] + feat[a1.y * D + jj]
                         + feat[a1.z * D + jj] + feat[a1.w * D + jj];
                float t2 = feat[a2.x * D + jj] + feat[a2.y * D + jj]
                         + feat[a2.z * D + jj] + feat[a2.w * D + jj];
                float t3 = feat[a3.x * D + jj] + feat[a3.y * D + jj]
                         + feat[a3.z * D + jj] + feat[a3.w * D + jj];
                nsum[s] = (t0 + t1) + (t2 + t3);
            }
            *(float4*)&xq[jj][kk * 4]     = make_float4(self[0], self[1], self[2], self[3]);
            *(float4*)&xq[D + jj][kk * 4] = make_float4(nsum[0], nsum[1], nsum[2], nsum[3]);
        }
        __syncthreads();                                 // A

        // ---------------- hop-1 GEMV: W in regs, x broadcast --------------
        {
            float acc[16];
            #pragma unroll
            for (int s = 0; s < 16; ++s) acc[s] = 0.f;
            #pragma unroll
            for (int m = 0; m < 32; ++m) {
                int i = kk * 32 + m;
                float w  = Wreg[m];
                float4 x0 = *(const float4*)&xq[i][0];   // all broadcast (1 phase)
                float4 x1 = *(const float4*)&xq[i][4];
                float4 x2 = *(const float4*)&xq[i][8];
                float4 x3 = *(const float4*)&xq[i][12];
                acc[0]  += w * x0.x; acc[1]  += w * x0.y;
                acc[2]  += w * x0.z; acc[3]  += w * x0.w;
                acc[4]  += w * x1.x; acc[5]  += w * x1.y;
                acc[6]  += w * x1.z; acc[7]  += w * x1.w;
                acc[8]  += w * x2.x; acc[9]  += w * x2.y;
                acc[10] += w * x2.z; acc[11] += w * x2.w;
                acc[12] += w * x3.x; acc[13] += w * x3.y;
                acc[14] += w * x3.z; acc[15] += w * x3.w;
            }
            *(float4*)&pr[kk][jj][0]  = make_float4(acc[0],  acc[1],  acc[2],  acc[3]);
            *(float4*)&pr[kk][jj][4]  = make_float4(acc[4],  acc[5],  acc[6],  acc[7]);
            *(float4*)&pr[kk][jj][8]  = make_float4(acc[8],  acc[9],  acc[10], acc[11]);
            *(float4*)&pr[kk][jj][12] = make_float4(acc[12], acc[13], acc[14], acc[15]);
        }
        __syncthreads();                                 // B

        // ---------------- reduce i-chunks, tanh, sum slot-quad ------------
        {
            float4 v0 = *(const float4*)&pr[0][jj][kk * 4];
            float4 v1 = *(const float4*)&pr[1][jj][kk * 4];
            float4 v2 = *(const float4*)&pr[2][jj][kk * 4];
            float4 v3 = *(const float4*)&pr[3][jj][kk * 4];
            float bb = b1s[jj];
            float t = tanhf((v0.x + v1.x) + (v2.x + v3.x) + bb)
                    + tanhf((v0.y + v1.y) + (v2.y + v3.y) + bb)
                    + tanhf((v0.z + v1.z) + (v2.z + v3.z) + bb)
                    + tanhf((v0.w + v1.w) + (v2.w + v3.w) + bb);
            part[kk][jj] = t;
        }
        __syncthreads();                                 // C

        if (tid < D)
            x2s[D + tid] = (part[0][tid] + part[1][tid])
                         + (part[2][tid] + part[3][tid]);
        __syncthreads();                                 // D

        // ---------------- hop-2 GEMV (W2 L1-resident across queries) -----
        {
            const float4* w2r = (const float4*)(W2 + col * (2 * D) + hlf * D);
            const float*  xh  = x2s + hlf * D;
            float acc = 0.f;
            #pragma unroll 8
            for (int i4 = 0; i4 < D / 4; ++i4) {
                float4 w = __ldg(&w2r[i4]);
                acc += w.x * xh[i4 * 4 + 0] + w.y * xh[i4 * 4 + 1]
                     + w.z * xh[i4 * 4 + 2] + w.w * xh[i4 * 4 + 3];
            }
            yp[hlf][col] = acc;
        }
        __syncthreads();                                 // E

        float y = 0.f;
        if (tid < D2) {
            y = yp[0][tid] + yp[1][tid] + b2[tid];
            float sq = y * y;
            #pragma unroll
            for (int off = 16; off; off >>= 1)
                sq += __shfl_xor_sync(0xffffffffu, sq, off);
            if ((tid & 31) == 0) red[tid >> 5] = sq;
        }
        __syncthreads();                                 // F

        if (tid < D2) {
            float tot = (red[0] + red[1]) + (red[2] + red[3]);
            out[q * D2 + tid] = y / fmaxf(sqrtf(tot), 1e-12f);
        }
        __syncthreads();                                 // G (protect reuse)
    }
}

// ---------------------------------------------------------------------------
extern "C" void kernel_launch(void* const* d_in, const int* in_sizes, int n_in,
                              void* d_out, int out_size) {
    const float* feat = (const float*)d_in[0];   // [65536, 64]
    const int*   adj  = (const int*)  d_in[1];   // [65536, 16]
    const int*   in1  = (const int*)  d_in[2];   // [1024]
    const int*   in2  = (const int*)  d_in[3];   // [1024]
    const int*   neg  = (const int*)  d_in[4];   // [10]
    const float* W1   = (const float*)d_in[5];   // [64, 128]
    const float* b1   = (const float*)d_in[6];   // [64]
    const float* W2   = (const float*)d_in[7];   // [128, 128]
    const float* b2   = (const float*)d_in[8];   // [128]
    float*       out  = (float*)d_out;           // [2058, 128]

    k_fused<<<GRID, 256>>>(feat, adj, in1, in2, neg, W1, b1, W2, b2, out);
}

// round 9
// speedup vs baseline: 1.5640x; 1.5640x over previous
#include <cuda_runtime.h>
#include <math.h>

#define DEG   16
#define D     64
#define D2    128
#define BQ    1024
#define NQ    2058
#define XPAD  20           /* slot-dim stride (words): conflict-free for 8-lane quads */
#define QPB   8            /* queries per block in hop2 */

__device__ float d_sum2[NQ * D];     // per-query summed hop-1 embeddings (527 KB)

__device__ __forceinline__ int qnode_of(int q,
                                        const int* __restrict__ in1,
                                        const int* __restrict__ in2,
                                        const int* __restrict__ neg) {
    return (q < BQ) ? in1[q] : (q < 2 * BQ) ? in2[q - BQ] : neg[q - 2 * BQ];
}

// ---------------------------------------------------------------------------
// 1) Per query q: gather 16 neighbor slots, hop-1 GEMV + tanh, reduce over
//    slots -> d_sum2[q][0..63].  256 thr = 64 cols (jj) x 4 i-chunks (kk).
// ---------------------------------------------------------------------------
__global__ __launch_bounds__(256, 3)
void k_h1(const float* __restrict__ feat,
          const int*   __restrict__ adj,
          const int*   __restrict__ in1,
          const int*   __restrict__ in2,
          const int*   __restrict__ neg,
          const float* __restrict__ W1,
          const float* __restrict__ b1) {
    __shared__ __align__(16) float xq[2 * D][XPAD];   // [i][slot]    10 KB
    __shared__ __align__(16) float pr[4][D][XPAD];    // chunk partials 20 KB
    __shared__ float part[4][D];                      // slot-quad tanh sums

    int tid = threadIdx.x;
    int jj  = tid & 63;          // hop-1 output column
    int kk  = tid >> 6;          // i-chunk / slot-quad (0..3)
    int q   = blockIdx.x;
    int qn  = qnode_of(q, in1, in2, neg);

    // ---- gather: group kk fills slots kk*4 .. kk*4+3 ----------------------
    {
        int4 nn4 = *(const int4*)(adj + qn * DEG + kk * 4);   // broadcast
        float self[4], nsum[4];
        #pragma unroll
        for (int s = 0; s < 4; ++s) {
            int node = (s == 0) ? nn4.x : (s == 1) ? nn4.y
                     : (s == 2) ? nn4.z : nn4.w;
            self[s] = feat[node * D + jj];
            const int4* a4 = (const int4*)(adj + node * DEG);
            int4 a0 = a4[0], a1 = a4[1], a2 = a4[2], a3 = a4[3];
            float t = feat[a0.x * D + jj] + feat[a0.y * D + jj]
                    + feat[a0.z * D + jj] + feat[a0.w * D + jj];
            t += feat[a1.x * D + jj] + feat[a1.y * D + jj]
               + feat[a1.z * D + jj] + feat[a1.w * D + jj];
            t += feat[a2.x * D + jj] + feat[a2.y * D + jj]
               + feat[a2.z * D + jj] + feat[a2.w * D + jj];
            t += feat[a3.x * D + jj] + feat[a3.y * D + jj]
               + feat[a3.z * D + jj] + feat[a3.w * D + jj];
            nsum[s] = t;
        }
        *(float4*)&xq[jj][kk * 4]     = make_float4(self[0], self[1], self[2], self[3]);
        *(float4*)&xq[D + jj][kk * 4] = make_float4(nsum[0], nsum[1], nsum[2], nsum[3]);
    }

    // ---- W1 chunk into registers (L1-hot after first blocks on the SM) ----
    float Wreg[32];
    {
        const float4* ws = (const float4*)(W1 + jj * (2 * D) + kk * 32);
        #pragma unroll
        for (int r = 0; r < 8; ++r) {
            float4 v = __ldg(&ws[r]);
            Wreg[r * 4 + 0] = v.x; Wreg[r * 4 + 1] = v.y;
            Wreg[r * 4 + 2] = v.z; Wreg[r * 4 + 3] = v.w;
        }
    }
    __syncthreads();                                   // A: xq ready

    // ---- GEMV: W in regs, x broadcast (1 phase per LDS.128) --------------
    {
        float acc[16];
        #pragma unroll
        for (int s = 0; s < 16; ++s) acc[s] = 0.f;
        #pragma unroll
        for (int m = 0; m < 32; ++m) {
            int i = kk * 32 + m;
            float w = Wreg[m];
            float4 x0 = *(const float4*)&xq[i][0];
            float4 x1 = *(const float4*)&xq[i][4];
            float4 x2 = *(const float4*)&xq[i][8];
            float4 x3 = *(const float4*)&xq[i][12];
            acc[0]  += w * x0.x; acc[1]  += w * x0.y;
            acc[2]  += w * x0.z; acc[3]  += w * x0.w;
            acc[4]  += w * x1.x; acc[5]  += w * x1.y;
            acc[6]  += w * x1.z; acc[7]  += w * x1.w;
            acc[8]  += w * x2.x; acc[9]  += w * x2.y;
            acc[10] += w * x2.z; acc[11] += w * x2.w;
            acc[12] += w * x3.x; acc[13] += w * x3.y;
            acc[14] += w * x3.z; acc[15] += w * x3.w;
        }
        *(float4*)&pr[kk][jj][0]  = make_float4(acc[0],  acc[1],  acc[2],  acc[3]);
        *(float4*)&pr[kk][jj][4]  = make_float4(acc[4],  acc[5],  acc[6],  acc[7]);
        *(float4*)&pr[kk][jj][8]  = make_float4(acc[8],  acc[9],  acc[10], acc[11]);
        *(float4*)&pr[kk][jj][12] = make_float4(acc[12], acc[13], acc[14], acc[15]);
    }
    __syncthreads();                                   // B: pr ready

    // ---- reduce i-chunks, +bias, tanh, sum slot-quad ---------------------
    {
        float4 v0 = *(const float4*)&pr[0][jj][kk * 4];
        float4 v1 = *(const float4*)&pr[1][jj][kk * 4];
        float4 v2 = *(const float4*)&pr[2][jj][kk * 4];
        float4 v3 = *(const float4*)&pr[3][jj][kk * 4];
        float bb = __ldg(&b1[jj]);
        part[kk][jj] = tanhf((v0.x + v1.x) + (v2.x + v3.x) + bb)
                     + tanhf((v0.y + v1.y) + (v2.y + v3.y) + bb)
                     + tanhf((v0.z + v1.z) + (v2.z + v3.z) + bb)
                     + tanhf((v0.w + v1.w) + (v2.w + v3.w) + bb);
    }
    __syncthreads();                                   // C: part ready

    if (tid < D)
        d_sum2[q * D + tid] = (part[0][tid] + part[1][tid])
                            + (part[2][tid] + part[3][tid]);
}

// ---------------------------------------------------------------------------
// 2) out[q] = normalize(concat(feat[qn], sum2[q]) @ W2^T + b2)
//    8 queries/block, 256 thr: halves 0/1 take queries 0..3 / 4..7 (full dot).
// ---------------------------------------------------------------------------
__global__ __launch_bounds__(256)
void k_hop2(const float* __restrict__ feat,
            const int*   __restrict__ in1,
            const int*   __restrict__ in2,
            const int*   __restrict__ neg,
            const float* __restrict__ W2,
            const float* __restrict__ b2,
            float*       __restrict__ out) {
    __shared__ __align__(16) float x2s[2 * D][12];   // [i][query] stride-12: conflict-free
    __shared__ __align__(16) float ys[QPB][D2 + 4];
    __shared__ float inv8[QPB];

    int tid = threadIdx.x;
    int qb  = blockIdx.x * QPB;
    int col = tid & 127;
    int hlf = tid >> 7;          // query-quad selector

    // ---- build x2s: thread (j,u): u=0/1 self q0-3/q4-7, u=2/3 sum2 -------
    {
        int j = tid & 63, u = tid >> 6;
        int qs = (u & 1) * 4;
        float v[4];
        #pragma unroll
        for (int s = 0; s < 4; ++s) {
            int q = qb + qs + s;
            if (q >= NQ) { v[s] = 0.f; continue; }
            if (u < 2) v[s] = feat[qnode_of(q, in1, in2, neg) * D + j];
            else       v[s] = d_sum2[q * D + j];
        }
        int row = (u < 2) ? j : D + j;
        *(float4*)&x2s[row][qs] = make_float4(v[0], v[1], v[2], v[3]);
    }
    __syncthreads();                                   // A

    // ---- GEMV: each half does 4 queries, full 128-dot --------------------
    float acc0, acc1, acc2, acc3;
    {
        float bb = b2[col];
        acc0 = acc1 = acc2 = acc3 = bb;
        const float4* wrow = (const float4*)(W2 + col * (2 * D));
        int qoff = hlf * 4;
        #pragma unroll 8
        for (int i4 = 0; i4 < (2 * D) / 4; ++i4) {
            float4 w = __ldg(&wrow[i4]);
            #pragma unroll
            for (int e = 0; e < 4; ++e) {
                float we = (e == 0) ? w.x : (e == 1) ? w.y
                         : (e == 2) ? w.z : w.w;
                float4 xv = *(const float4*)&x2s[i4 * 4 + e][qoff];  // broadcast
                acc0 += we * xv.x; acc1 += we * xv.y;
                acc2 += we * xv.z; acc3 += we * xv.w;
            }
        }
        ys[qoff + 0][col] = acc0;
        ys[qoff + 1][col] = acc1;
        ys[qoff + 2][col] = acc2;
        ys[qoff + 3][col] = acc3;
    }
    __syncthreads();                                   // B

    {   // warp w reduces query w's squared norm
        int w = tid >> 5, l = tid & 31;
        float v = ys[w][l]      * ys[w][l]
                + ys[w][l + 32] * ys[w][l + 32]
                + ys[w][l + 64] * ys[w][l + 64]
                + ys[w][l + 96] * ys[w][l + 96];
        #pragma unroll
        for (int off = 16; off; off >>= 1)
            v += __shfl_xor_sync(0xffffffffu, v, off);
        if (l == 0) inv8[w] = 1.0f / fmaxf(sqrtf(v), 1e-12f);
    }
    __syncthreads();                                   // C

    {
        int qoff = hlf * 4;
        if (qb + qoff + 0 < NQ) out[(qb + qoff + 0) * D2 + col] = acc0 * inv8[qoff + 0];
        if (qb + qoff + 1 < NQ) out[(qb + qoff + 1) * D2 + col] = acc1 * inv8[qoff + 1];
        if (qb + qoff + 2 < NQ) out[(qb + qoff + 2) * D2 + col] = acc2 * inv8[qoff + 2];
        if (qb + qoff + 3 < NQ) out[(qb + qoff + 3) * D2 + col] = acc3 * inv8[qoff + 3];
    }
}

// ---------------------------------------------------------------------------
extern "C" void kernel_launch(void* const* d_in, const int* in_sizes, int n_in,
                              void* d_out, int out_size) {
    const float* feat = (const float*)d_in[0];   // [65536, 64]
    const int*   adj  = (const int*)  d_in[1];   // [65536, 16]
    const int*   in1  = (const int*)  d_in[2];   // [1024]
    const int*   in2  = (const int*)  d_in[3];   // [1024]
    const int*   neg  = (const int*)  d_in[4];   // [10]
    const float* W1   = (const float*)d_in[5];   // [64, 128]
    const float* b1   = (const float*)d_in[6];   // [64]
    const float* W2   = (const float*)d_in[7];   // [128, 128]
    const float* b2   = (const float*)d_in[8];   // [128]
    float*       out  = (float*)d_out;           // [2058, 128]

    k_h1<<<NQ, 256>>>(feat, adj, in1, in2, neg, W1, b1);
    k_hop2<<<(NQ + QPB - 1) / QPB, 256>>>(feat, in1, in2, neg, W2, b2, out);
}

// round 10
// speedup vs baseline: 1.8863x; 1.2061x over previous
#include <cuda_runtime.h>
#include <math.h>

#define DEG   16
#define D     64
#define D2    128
#define BQ    1024
#define NQ    2058
#define XPAD  20           /* slot-dim stride (words): conflict-free quads */
#define GRID  (NQ / 2)     /* 1029 blocks, 2 queries each, exact */

__device__ __forceinline__ int qnode_of(int q,
                                        const int* __restrict__ in1,
                                        const int* __restrict__ in2,
                                        const int* __restrict__ neg) {
    return (q < BQ) ? in1[q] : (q < 2 * BQ) ? in2[q - BQ] : neg[q - 2 * BQ];
}

// ---------------------------------------------------------------------------
__global__ __launch_bounds__(256, 3)
void k_all(const float* __restrict__ feat,
           const int*   __restrict__ adj,
           const int*   __restrict__ in1,
           const int*   __restrict__ in2,
           const int*   __restrict__ neg,
           const float* __restrict__ W1,
           const float* __restrict__ b1,
           const float* __restrict__ W2,
           const float* __restrict__ b2,
           float*       __restrict__ out) {
    __shared__ __align__(16) float xq[2][2 * D][XPAD];  // [q][i][slot] 20.5 KB
    __shared__ __align__(16) float pr[4][D][XPAD];      // chunk partials 20 KB
    __shared__ __align__(16) float part[2][4][D];       // tanh slot-quad sums
    __shared__ __align__(16) float x2[2][2 * D];        // hop-2 inputs
    __shared__ __align__(16) float ys[2][D2];           // hop-2 outputs
    __shared__ float red[2][8];
    __shared__ float inv2[2];

    int tid  = threadIdx.x;
    int jj   = tid & 63;         // hop-1 output column
    int kk   = tid >> 6;         // i-chunk / slot-quad (0..3)
    int lane = tid & 31;
    int wrp  = tid >> 5;         // 0..7
    int qa   = blockIdx.x * 2;
    int na   = qnode_of(qa,     in1, in2, neg);
    int nb   = qnode_of(qa + 1, in1, in2, neg);

    // ---- self features for hop-2 -----------------------------------------
    if (tid < D)            x2[0][tid]     = feat[na * D + tid];
    else if (tid < 2 * D)   x2[1][tid - D] = feat[nb * D + (tid - D)];

    // ---- gather both queries: group kk fills slots kk*4..kk*4+3 ----------
    #pragma unroll
    for (int sel = 0; sel < 2; ++sel) {
        int qn = sel ? nb : na;
        int4 nn4 = *(const int4*)(adj + qn * DEG + kk * 4);   // broadcast
        float self[4], nsum[4];
        #pragma unroll
        for (int s = 0; s < 4; ++s) {
            int node = (s == 0) ? nn4.x : (s == 1) ? nn4.y
                     : (s == 2) ? nn4.z : nn4.w;
            self[s] = feat[node * D + jj];
            const int4* a4 = (const int4*)(adj + node * DEG);
            int4 a0 = a4[0], a1 = a4[1], a2 = a4[2], a3 = a4[3];
            float t = feat[a0.x * D + jj] + feat[a0.y * D + jj]
                    + feat[a0.z * D + jj] + feat[a0.w * D + jj];
            t += feat[a1.x * D + jj] + feat[a1.y * D + jj]
               + feat[a1.z * D + jj] + feat[a1.w * D + jj];
            t += feat[a2.x * D + jj] + feat[a2.y * D + jj]
               + feat[a2.z * D + jj] + feat[a2.w * D + jj];
            t += feat[a3.x * D + jj] + feat[a3.y * D + jj]
               + feat[a3.z * D + jj] + feat[a3.w * D + jj];
            nsum[s] = t;
        }
        *(float4*)&xq[sel][jj][kk * 4]     = make_float4(self[0], self[1], self[2], self[3]);
        *(float4*)&xq[sel][D + jj][kk * 4] = make_float4(nsum[0], nsum[1], nsum[2], nsum[3]);
    }

    // ---- W1 chunk into registers -----------------------------------------
    float Wreg[32];
    {
        const float4* ws = (const float4*)(W1 + jj * (2 * D) + kk * 32);
        #pragma unroll
        for (int r = 0; r < 8; ++r) {
            float4 v = __ldg(&ws[r]);
            Wreg[r * 4 + 0] = v.x; Wreg[r * 4 + 1] = v.y;
            Wreg[r * 4 + 2] = v.z; Wreg[r * 4 + 3] = v.w;
        }
    }
    __syncthreads();                                    // A: xq ready

    float bb1 = __ldg(&b1[jj]);

    #pragma unroll
    for (int sel = 0; sel < 2; ++sel) {
        // ---- GEMV: W in regs, x broadcast --------------------------------
        {
            float acc[16];
            #pragma unroll
            for (int s = 0; s < 16; ++s) acc[s] = 0.f;
            #pragma unroll
            for (int m = 0; m < 32; ++m) {
                int i = kk * 32 + m;
                float w = Wreg[m];
                float4 x0 = *(const float4*)&xq[sel][i][0];
                float4 x1 = *(const float4*)&xq[sel][i][4];
                float4 x2v = *(const float4*)&xq[sel][i][8];
                float4 x3 = *(const float4*)&xq[sel][i][12];
                acc[0]  += w * x0.x;  acc[1]  += w * x0.y;
                acc[2]  += w * x0.z;  acc[3]  += w * x0.w;
                acc[4]  += w * x1.x;  acc[5]  += w * x1.y;
                acc[6]  += w * x1.z;  acc[7]  += w * x1.w;
                acc[8]  += w * x2v.x; acc[9]  += w * x2v.y;
                acc[10] += w * x2v.z; acc[11] += w * x2v.w;
                acc[12] += w * x3.x;  acc[13] += w * x3.y;
                acc[14] += w * x3.z;  acc[15] += w * x3.w;
            }
            *(float4*)&pr[kk][jj][0]  = make_float4(acc[0],  acc[1],  acc[2],  acc[3]);
            *(float4*)&pr[kk][jj][4]  = make_float4(acc[4],  acc[5],  acc[6],  acc[7]);
            *(float4*)&pr[kk][jj][8]  = make_float4(acc[8],  acc[9],  acc[10], acc[11]);
            *(float4*)&pr[kk][jj][12] = make_float4(acc[12], acc[13], acc[14], acc[15]);
        }
        __syncthreads();                                // B/D: pr ready

        // ---- reduce chunks, +bias, tanh, sum slot-quad -------------------
        {
            float4 v0 = *(const float4*)&pr[0][jj][kk * 4];
            float4 v1 = *(const float4*)&pr[1][jj][kk * 4];
            float4 v2 = *(const float4*)&pr[2][jj][kk * 4];
            float4 v3 = *(const float4*)&pr[3][jj][kk * 4];
            part[sel][kk][jj] = tanhf((v0.x + v1.x) + (v2.x + v3.x) + bb1)
                              + tanhf((v0.y + v1.y) + (v2.y + v3.y) + bb1)
                              + tanhf((v0.z + v1.z) + (v2.z + v3.z) + bb1)
                              + tanhf((v0.w + v1.w) + (v2.w + v3.w) + bb1);
        }
        __syncthreads();                                // C/E: pr reusable
    }

    // ---- build hop-2 inputs ----------------------------------------------
    if (tid < D) {
        x2[0][D + tid] = (part[0][0][tid] + part[0][1][tid])
                       + (part[0][2][tid] + part[0][3][tid]);
    } else if (tid < 2 * D) {
        int j = tid - D;
        x2[1][D + j] = (part[1][0][j] + part[1][1][j])
                     + (part[1][2][j] + part[1][3][j]);
    }
    __syncthreads();                                    // F: x2 ready

    // ---- hop-2: warp w handles cols w*16..w*16+15, both queries ----------
    {
        float sqa = 0.f, sqb = 0.f;
        float4 xa = *(const float4*)&x2[0][lane * 4];   // lane-consecutive LDS.128
        float4 xb = *(const float4*)&x2[1][lane * 4];
        #pragma unroll 4
        for (int c0 = 0; c0 < 16; ++c0) {
            int c = wrp * 16 + c0;
            float4 wv = __ldg((const float4*)(W2 + c * (2 * D)) + lane); // coalesced
            float pa = wv.x * xa.x + wv.y * xa.y + wv.z * xa.z + wv.w * xa.w;
            float pb = wv.x * xb.x + wv.y * xb.y + wv.z * xb.z + wv.w * xb.w;
            #pragma unroll
            for (int off = 16; off; off >>= 1) {
                pa += __shfl_xor_sync(0xffffffffu, pa, off);
                pb += __shfl_xor_sync(0xffffffffu, pb, off);
            }
            float bbc = __ldg(&b2[c]);
            pa += bbc; pb += bbc;
            sqa += pa * pa; sqb += pb * pb;
            if (lane == 0) { ys[0][c] = pa; ys[1][c] = pb; }
        }
        if (lane == 0) { red[0][wrp] = sqa; red[1][wrp] = sqb; }
    }
    __syncthreads();                                    // G: ys/red ready

    if (tid < 2) {
        float t = ((red[tid][0] + red[tid][1]) + (red[tid][2] + red[tid][3]))
                + ((red[tid][4] + red[tid][5]) + (red[tid][6] + red[tid][7]));
        inv2[tid] = 1.0f / fmaxf(sqrtf(t), 1e-12f);
    }
    __syncthreads();                                    // H: inv ready

    {
        int qsel = tid >> 7;
        int col  = tid & 127;
        out[(qa + qsel) * D2 + col] = ys[qsel][col] * inv2[qsel];
    }
}

// ---------------------------------------------------------------------------
extern "C" void kernel_launch(void* const* d_in, const int* in_sizes, int n_in,
                              void* d_out, int out_size) {
    const float* feat = (const float*)d_in[0];   // [65536, 64]
    const int*   adj  = (const int*)  d_in[1];   // [65536, 16]
    const int*   in1  = (const int*)  d_in[2];   // [1024]
    const int*   in2  = (const int*)  d_in[3];   // [1024]
    const int*   neg  = (const int*)  d_in[4];   // [10]
    const float* W1   = (const float*)d_in[5];   // [64, 128]
    const float* b1   = (const float*)d_in[6];   // [64]
    const float* W2   = (const float*)d_in[7];   // [128, 128]
    const float* b2   = (const float*)d_in[8];   // [128]
    float*       out  = (float*)d_out;           // [2058, 128]

    k_all<<<GRID, 256>>>(feat, adj, in1, in2, neg, W1, b1, W2, b2, out);
}